// round 14
// baseline (speedup 1.0000x reference)
#include <cuda_runtime.h>
#include <cuda_fp16.h>
#include <cstdint>

// ---------------------------------------------------------------------------
// pointwise (Bahdanau additive) attention, fp32 via fp16 mma.sync HMMA
// B=32, T=2048, D=512, U=512
// out layout: [0, B*D) = context ; [B*D, B*D + B*T) = attn
// Round 13: hsplit deleted. Score GEMM loads raw fp32 A via cp.async and
// converts to fp16 in-pipeline (KC=32, raw x3 / Bh x4 / Ah x2 stages,
// lookahead-2, 1 sync/chunk). ut==0 CTAs persist converted A to g_Ah for
// the context kernel (write hides under compute).
// ---------------------------------------------------------------------------

#define CB 32
#define CT 2048
#define CD 512
#define CU 512

// scratch (allocation-free rule: __device__ globals)
__device__ float g_scores[CB * CT];
__device__ float g_dec_proj[CB * CU];
__device__ __half g_W1h[CU * CD];               // transposed: [u][k], fp16
__device__ __half g_Ah[(size_t)CB * CT * CD];   // h_enc fp16 (written by score)

// -------------------- PTX helpers --------------------
__device__ __forceinline__ uint32_t smem_u32(const void* p) {
    uint32_t a;
    asm("{ .reg .u64 t; cvta.to.shared.u64 t, %1; cvt.u32.u64 %0, t; }"
        : "=r"(a) : "l"(p));
    return a;
}
__device__ __forceinline__ void cp16(uint32_t dst, const void* src) {
    asm volatile("cp.async.cg.shared.global [%0], [%1], 16;"
                 :: "r"(dst), "l"(src) : "memory");
}
__device__ __forceinline__ uint32_t packh2(float a, float b) {
    uint32_t r;                                   // low=a, high=b
    asm("cvt.rn.f16x2.f32 %0, %1, %2;" : "=r"(r) : "f"(b), "f"(a));
    return r;
}
__device__ __forceinline__ float fast_tanh(float x) {
    float e;
    asm("ex2.approx.f32 %0, %1;" : "=f"(e) : "f"(x * 2.885390081777927f)); // e^(2x)
    float r;
    asm("rcp.approx.f32 %0, %1;" : "=f"(r) : "f"(e + 1.0f));
    return fmaf(-2.0f, r, 1.0f);
}

#define LDSM4(r, addr)                                                        \
    asm volatile("ldmatrix.sync.aligned.m8n8.x4.shared.b16 {%0,%1,%2,%3}, [%4];" \
                 : "=r"((r)[0]), "=r"((r)[1]), "=r"((r)[2]), "=r"((r)[3])     \
                 : "r"(addr))

#define MMAH(d, a, b0, b1)                                                    \
    asm volatile("mma.sync.aligned.m16n8k16.row.col.f32.f16.f16.f32 "         \
                 "{%0,%1,%2,%3}, {%4,%5,%6,%7}, {%8,%9}, {%0,%1,%2,%3};"      \
                 : "+f"((d)[0]), "+f"((d)[1]), "+f"((d)[2]), "+f"((d)[3])     \
                 : "r"((a)[0]), "r"((a)[1]), "r"((a)[2]), "r"((a)[3]),        \
                   "r"(b0), "r"(b1))

// -------------------- kernel 0: prep (w1conv + dec_proj + zero scores) -----
#define WC_BLOCKS 256
#define PREP_GRID (WC_BLOCKS + 64)

__global__ __launch_bounds__(256)
void fused_prep_kernel(const float* __restrict__ W1,
                       const float* __restrict__ h_dec,
                       const float* __restrict__ b1) {
    const int blk = blockIdx.x;
    const int tid = threadIdx.x;
    __shared__ float sh[32][33];            // w1conv transpose / prep hd

    if (blk < WC_BLOCKS) {
        const int u0 = (blk & 15) * 32, k0 = (blk >> 4) * 32;
        const int tx = tid & 31, ty = tid >> 5;
#pragma unroll
        for (int i = 0; i < 4; i++)
            sh[ty + i * 8][tx] = W1[(size_t)(k0 + ty + i * 8) * CU + u0 + tx];
        __syncthreads();
#pragma unroll
        for (int i = 0; i < 4; i++)
            g_W1h[(size_t)(u0 + ty + i * 8) * CD + k0 + tx] =
                __float2half_rn(sh[tx][ty + i * 8]);
    } else {
        const int id = blk - WC_BLOCKS;
        const int b = id >> 1, uh = id & 1;
        float* hd = &sh[0][0];              // 512 floats
        hd[tid] = h_dec[b * CD + tid];
        hd[tid + 256] = h_dec[b * CD + tid + 256];
        __syncthreads();
        const int u = uh * 256 + tid;
        float a0 = b1[u], a1 = 0.f, a2 = 0.f, a3 = 0.f;
        float a4 = 0.f, a5 = 0.f, a6 = 0.f, a7 = 0.f;
#pragma unroll 4
        for (int k = 0; k < CD; k += 8) {
            a0 += hd[k + 0] * W1[(size_t)(CD + k + 0) * CU + u];
            a1 += hd[k + 1] * W1[(size_t)(CD + k + 1) * CU + u];
            a2 += hd[k + 2] * W1[(size_t)(CD + k + 2) * CU + u];
            a3 += hd[k + 3] * W1[(size_t)(CD + k + 3) * CU + u];
            a4 += hd[k + 4] * W1[(size_t)(CD + k + 4) * CU + u];
            a5 += hd[k + 5] * W1[(size_t)(CD + k + 5) * CU + u];
            a6 += hd[k + 6] * W1[(size_t)(CD + k + 6) * CU + u];
            a7 += hd[k + 7] * W1[(size_t)(CD + k + 7) * CU + u];
        }
        g_dec_proj[b * CU + u] =
            ((a0 + a1) + (a2 + a3)) + ((a4 + a5) + (a6 + a7));
#pragma unroll
        for (int t = uh * 1024 + tid; t < uh * 1024 + 1024; t += 256)
            g_scores[b * CT + t] = 0.f;
    }
}

// -------------------- kernel 1: HMMA fp16 score GEMM (in-pipe convert) -----
// CTA tile: 128 t x 128 u, K=512 in 16 chunks of 32.
// smem: raw fp32 A x3 (16KB each) | Bh x4 (8KB) | Ah x2 (8KB) | dp | w2
#define SM_RAW  0
#define RAW_SZ  16384
#define SM_BHS  49152
#define BH_SZ   8192
#define SM_AHS  81920
#define AH_SZ   8192
#define SM_DP   98304
#define SM_W2   98816
#define SM_TOT  99328

__global__ __launch_bounds__(256, 2)
void score_kernel(const float* __restrict__ h_enc, const float* __restrict__ W2) {
    extern __shared__ char smem[];
    const uint32_t sbase = smem_u32(smem);
    const int tid = threadIdx.x;
    const int wid = tid >> 5, lid = tid & 31;
    const int wm = wid >> 1, wn = wid & 1;
    const int b = blockIdx.y;
    const int ut = blockIdx.x & 3, tt = blockIdx.x >> 2;  // u-fastest: A L2-hot
    const int t0 = tt * 128, u0 = ut * 128;
    const size_t arow = (size_t)(b * CT + t0);

    // per-lane ldmatrix geometry (fp16 tiles, 64B rows, SW64 XOR)
    const int rowAf = wm * 32 + (lid & 7) + ((lid >> 3) & 1) * 8;
    const int kselA = lid >> 4;
    const int rowBf = wn * 64 + (lid & 7) + (lid >> 4) * 8;
    const int kselB = (lid >> 3) & 1;

    uint32_t aoffs[2], boffs[2];
#pragma unroll
    for (int ks = 0; ks < 2; ks++) {
        aoffs[ks] = rowAf * 64 +
                    (((ks * 2 + kselA) ^ ((rowAf >> 1) & 3)) << 4);
        boffs[ks] = rowBf * 64 +
                    (((ks * 2 + kselB) ^ ((rowBf >> 1) & 3)) << 4);
    }

    // cp.async geometry
    // A raw: q<4: row = q*32 + (tid>>3), ch = tid&7 (16B of 128B fp32 row)
    const int arA = tid >> 3, achA = tid & 7;
    const uint32_t dA0 = arA * 128 + ((achA ^ (arA & 7)) << 4);
    const float* aP = h_enc + (arow + arA) * CD + achA * 4;
    // B: q<2: row = q*64 + (tid>>2), ch = tid&3 (16B of 64B fp16 row)
    const int brB = tid >> 2, bchB = tid & 3;
    const uint32_t dB0 = brB * 64 + ((bchB ^ ((brB >> 1) & 3)) << 4);
    const __half* bP = g_W1h + (size_t)(u0 + brB) * CD + bchB * 8;

    float* sdp = (float*)(smem + SM_DP);
    float* sw2 = (float*)(smem + SM_W2);
    if (tid < 128) {
        sdp[tid] = g_dec_proj[b * CU + u0 + tid];
        sw2[tid] = W2[u0 + tid];
    }

    auto load_chunk = [&](int c) {
        const uint32_t rawS = sbase + SM_RAW + (c % 3) * RAW_SZ;
        const uint32_t bhS  = sbase + SM_BHS + (c & 3) * BH_SZ;
        const int k0 = c * 32;
#pragma unroll
        for (int q = 0; q < 4; q++)
            cp16(rawS + dA0 + q * 4096, aP + (size_t)q * 32 * CD + k0);
#pragma unroll
        for (int q = 0; q < 2; q++)
            cp16(bhS + dB0 + q * 4096, bP + (size_t)q * 64 * CD + k0);
        asm volatile("cp.async.commit_group;" ::: "memory");
    };

    const int crow = tid >> 1, chalf = tid & 1;   // convert mapping
    auto convert_chunk = [&](int c) {
        const uint32_t rawS = sbase + SM_RAW + (c % 3) * RAW_SZ;
        const uint32_t ahS  = sbase + SM_AHS + (c & 1) * AH_SZ;
        uint32_t uh[8];
#pragma unroll
        for (int j = 0; j < 4; j++) {
            int ch = chalf * 4 + j;
            uint32_t a = rawS + crow * 128 + ((ch ^ (crow & 7)) << 4);
            float x, y, z, w;
            asm volatile("ld.shared.v4.f32 {%0,%1,%2,%3}, [%4];"
                         : "=f"(x), "=f"(y), "=f"(z), "=f"(w) : "r"(a));
            uh[j * 2]     = packh2(x, y);
            uh[j * 2 + 1] = packh2(z, w);
        }
#pragma unroll
        for (int jj = 0; jj < 2; jj++) {
            uint32_t d = ahS + crow * 64 +
                         (((chalf * 2 + jj) ^ ((crow >> 1) & 3)) << 4);
            asm volatile("st.shared.v4.b32 [%0], {%1,%2,%3,%4};"
                         :: "r"(d), "r"(uh[jj * 4]), "r"(uh[jj * 4 + 1]),
                            "r"(uh[jj * 4 + 2]), "r"(uh[jj * 4 + 3]));
        }
        if (ut == 0) {          // persist fp16 A for the context kernel
            __half* gp = g_Ah + (arow + crow) * CD + c * 32 + chalf * 16;
            *(uint4*)gp = make_uint4(uh[0], uh[1], uh[2], uh[3]);
            *(uint4*)(gp + 8) = make_uint4(uh[4], uh[5], uh[6], uh[7]);
        }
    };

    // ---- prologue: lookahead-2 ----
    load_chunk(0);
    load_chunk(1);
    load_chunk(2);
    asm volatile("cp.async.wait_group 2;" ::: "memory");   // chunk 0 arrived
    __syncthreads();
    convert_chunk(0);

    float acc[2][8][4];
#pragma unroll
    for (int mt = 0; mt < 2; mt++)
#pragma unroll
        for (int nt = 0; nt < 8; nt++)
#pragma unroll
            for (int j = 0; j < 4; j++) acc[mt][nt][j] = 0.f;

#pragma unroll 1
    for (int c = 0; c < 16; c++) {
        if (c + 1 < 16) {
            if (c + 2 < 16)
                asm volatile("cp.async.wait_group 1;" ::: "memory");
            else
                asm volatile("cp.async.wait_group 0;" ::: "memory");
        }
        __syncthreads();
        if (c + 3 < 16) load_chunk(c + 3);
        if (c + 1 < 16) convert_chunk(c + 1);

        // ---- MMA chunk c ----
        const uint32_t ahS = sbase + SM_AHS + (c & 1) * AH_SZ;
        const uint32_t bhS = sbase + SM_BHS + (c & 3) * BH_SZ;
#pragma unroll
        for (int ks = 0; ks < 2; ks++) {
            uint32_t aH[2][4], bH[4][4];
#pragma unroll
            for (int mt = 0; mt < 2; mt++)
                LDSM4(aH[mt], ahS + aoffs[ks] + mt * 1024);
#pragma unroll
            for (int ng = 0; ng < 4; ng++)
                LDSM4(bH[ng], bhS + boffs[ks] + ng * 1024);
#pragma unroll
            for (int ng = 0; ng < 4; ng++)
#pragma unroll
                for (int mt = 0; mt < 2; mt++) {
                    MMAH(acc[mt][2 * ng],     aH[mt], bH[ng][0], bH[ng][1]);
                    MMAH(acc[mt][2 * ng + 1], aH[mt], bH[ng][2], bH[ng][3]);
                }
        }
    }

    // ---- epilogue: scores[row] += sum_u tanh(acc + dp[u]) * w2[u] ----
    const int lid4 = lid & 3, lg = lid >> 2;
    const int ulb = wn * 64 + lid4 * 2;
#pragma unroll
    for (int mt = 0; mt < 2; mt++) {
        float s0 = 0.f, s1 = 0.f;
#pragma unroll
        for (int nt = 0; nt < 8; nt++) {
            int ul = ulb + nt * 8;
            float d0 = sdp[ul], d1 = sdp[ul + 1];
            float w0 = sw2[ul], w1 = sw2[ul + 1];
            s0 += fast_tanh(acc[mt][nt][0] + d0) * w0 +
                  fast_tanh(acc[mt][nt][1] + d1) * w1;
            s1 += fast_tanh(acc[mt][nt][2] + d0) * w0 +
                  fast_tanh(acc[mt][nt][3] + d1) * w1;
        }
        s0 += __shfl_xor_sync(0xffffffffu, s0, 1);
        s0 += __shfl_xor_sync(0xffffffffu, s0, 2);
        s1 += __shfl_xor_sync(0xffffffffu, s1, 1);
        s1 += __shfl_xor_sync(0xffffffffu, s1, 2);
        if (lid4 == 0) {
            int r = wm * 32 + mt * 16 + lg;
            atomicAdd(&g_scores[b * CT + t0 + r], s0);
            atomicAdd(&g_scores[b * CT + t0 + r + 8], s1);
        }
    }
}

// -------------------- kernel 2: softmax (+ b2, relu) + zero context --------
__global__ void softmax_kernel(const float* __restrict__ b2, float* __restrict__ out) {
    const int b = blockIdx.x;
    const int tid = threadIdx.x;
    const int wid = tid >> 5, lid = tid & 31;
    __shared__ float wredm[8], wreds[8];
    const float b2v = b2[0];
    float sv[8];

    float mx = 0.f;                        // relu -> scores >= 0
#pragma unroll
    for (int q = 0; q < 8; q++) {
        float s = g_scores[b * CT + q * 256 + tid] + b2v;
        s = s > 0.f ? s : 0.f;
        sv[q] = s;
        mx = fmaxf(mx, s);
    }
#pragma unroll
    for (int off = 16; off >= 1; off >>= 1)
        mx = fmaxf(mx, __shfl_xor_sync(0xffffffffu, mx, off));
    if (lid == 0) wredm[wid] = mx;
    __syncthreads();
    float m = wredm[0];
#pragma unroll
    for (int i = 1; i < 8; i++) m = fmaxf(m, wredm[i]);

    float sum = 0.f;
#pragma unroll
    for (int q = 0; q < 8; q++) {
        float e = expf(sv[q] - m);
        sv[q] = e;
        sum += e;
    }
#pragma unroll
    for (int off = 16; off >= 1; off >>= 1)
        sum += __shfl_xor_sync(0xffffffffu, sum, off);
    if (lid == 0) wreds[wid] = sum;
    __syncthreads();
    float tot = 0.f;
#pragma unroll
    for (int i = 0; i < 8; i++) tot += wreds[i];
    const float inv = 1.f / tot;

    float* attn = out + (size_t)CB * CD + (size_t)b * CT;
#pragma unroll
    for (int q = 0; q < 8; q++) attn[q * 256 + tid] = sv[q] * inv;

    for (int i = tid; i < CD; i += 256) out[b * CD + i] = 0.f;
}

// -------------------- kernel 3: context = sum_t attn * h_enc(fp16) ---------
__global__ __launch_bounds__(256)
void context_kernel(float* __restrict__ out) {
    const int b = blockIdx.y;
    const int t0 = blockIdx.x * 128;
    const int tid = threadIdx.x;
    const int dslot = tid & 63;            // d = dslot*8
    const int grp = tid >> 6;              // rows [grp*32, grp*32+32)
    __shared__ float at[128];
    __shared__ float sred[2][512];
    if (tid < 128) at[tid] = out[(size_t)CB * CD + (size_t)b * CT + t0 + tid];
    __syncthreads();

    const __half* hp = g_Ah + ((size_t)(b * CT + t0 + grp * 32)) * CD + dslot * 8;
    float acc[8];
#pragma unroll
    for (int k = 0; k < 8; k++) acc[k] = 0.f;

#pragma unroll 1
    for (int tt = 0; tt < 32; tt += 8) {
        uint4 hv[8];
#pragma unroll
        for (int j = 0; j < 8; j++)
            hv[j] = *(const uint4*)(hp + (size_t)(tt + j) * CD);
        float a[8];
#pragma unroll
        for (int j = 0; j < 8; j++) a[j] = at[grp * 32 + tt + j];
#pragma unroll
        for (int j = 0; j < 8; j++) {
            float2 f0 = __half22float2(*(__half2*)&hv[j].x);
            float2 f1 = __half22float2(*(__half2*)&hv[j].y);
            float2 f2 = __half22float2(*(__half2*)&hv[j].z);
            float2 f3 = __half22float2(*(__half2*)&hv[j].w);
            acc[0] += a[j] * f0.x;  acc[1] += a[j] * f0.y;
            acc[2] += a[j] * f1.x;  acc[3] += a[j] * f1.y;
            acc[4] += a[j] * f2.x;  acc[5] += a[j] * f2.y;
            acc[6] += a[j] * f3.x;  acc[7] += a[j] * f3.y;
        }
    }

    if (grp >= 2) {
#pragma unroll
        for (int k = 0; k < 8; k++) sred[grp - 2][dslot * 8 + k] = acc[k];
    }
    __syncthreads();
    if (grp < 2) {
#pragma unroll
        for (int k = 0; k < 8; k++) acc[k] += sred[grp][dslot * 8 + k];
    }
    __syncthreads();
    if (grp == 1) {
#pragma unroll
        for (int k = 0; k < 8; k++) sred[0][dslot * 8 + k] = acc[k];
    }
    __syncthreads();
    if (grp == 0) {
        float* cp = out + (size_t)b * CD + dslot * 8;
#pragma unroll
        for (int k = 0; k < 8; k++)
            atomicAdd(cp + k, acc[k] + sred[0][dslot * 8 + k]);
    }
}

// -------------------- host launcher --------------------
extern "C" void kernel_launch(void* const* d_in, const int* in_sizes, int n_in,
                              void* d_out, int out_size) {
    const float* h_enc = (const float*)d_in[0];
    const float* h_dec = (const float*)d_in[1];
    const float* W1    = (const float*)d_in[2];
    const float* b1    = (const float*)d_in[3];
    const float* W2    = (const float*)d_in[4];
    const float* b2    = (const float*)d_in[5];
    float* out = (float*)d_out;

    cudaFuncSetAttribute(score_kernel,
                         cudaFuncAttributeMaxDynamicSharedMemorySize, SM_TOT);

    fused_prep_kernel<<<PREP_GRID, 256>>>(W1, h_dec, b1);
    score_kernel<<<dim3(64, CB), 256, SM_TOT>>>(h_enc, W2);
    softmax_kernel<<<CB, 256>>>(b2, out);
    context_kernel<<<dim3(CT / 128, CB), 256>>>(out);
}